// round 15
// baseline (speedup 1.0000x reference)
#include <cuda_runtime.h>
#include <cstdint>

#define Bn      8
#define Nn      8192
#define NPOINT  1024
#define NSAMPLE 32
#define PPT     8          // points per thread in FPS (Nn / 1024)

#define FEAT_BLOCKS 32
#define FEAT_PTS    ((Bn * Nn) / FEAT_BLOCKS)   // 2048 points per feat block
#define CONS_BLOCKS 104
#define CONS_WARPS  (CONS_BLOCKS * 32)          // 3328 consumer warps
#define GRID_TOTAL  (Bn + FEAT_BLOCKS + CONS_BLOCKS)   // 144 <= 148: wave-1

typedef unsigned long long ull;

// feature table + sync cells
__device__ float4 g_feat4[Bn * Nn * 32];   // 33.5 MB, row = point, 32 x float4
__device__ int    g_progress[Bn];          // centers published per batch
__device__ int    g_feat_done;             // feat blocks completed

// ---------------------------------------------------------------------------
// packed f32x2 helpers — each half rounds exactly like the scalar .rn op
// ---------------------------------------------------------------------------
__device__ __forceinline__ ull pack2(float lo, float hi) {
    ull r; asm("mov.b64 %0, {%1,%2};" : "=l"(r) : "f"(lo), "f"(hi)); return r;
}
__device__ __forceinline__ void unpack2(ull v, float& lo, float& hi) {
    asm("mov.b64 {%0,%1}, %2;" : "=f"(lo), "=f"(hi) : "l"(v));
}
__device__ __forceinline__ ull add2(ull a, ull b) {
    ull r; asm("add.rn.f32x2 %0,%1,%2;" : "=l"(r) : "l"(a), "l"(b)); return r;
}
__device__ __forceinline__ ull mul2(ull a, ull b) {
    ull r; asm("mul.rn.f32x2 %0,%1,%2;" : "=l"(r) : "l"(a), "l"(b)); return r;
}
__device__ __forceinline__ ull fma2(ull a, ull b, ull c) {
    ull r; asm("fma.rn.f32x2 %0,%1,%2,%3;" : "=l"(r) : "l"(a), "l"(b), "l"(c)); return r;
}

// ---------------------------------------------------------------------------
// gmem release/acquire helpers
// ---------------------------------------------------------------------------
__device__ __forceinline__ int ld_acquire(const int* p) {
    int v; asm volatile("ld.acquire.gpu.global.s32 %0, [%1];" : "=r"(v) : "l"(p) : "memory");
    return v;
}
__device__ __forceinline__ void st_release(int* p, int v) {
    asm volatile("st.release.gpu.global.s32 [%0], %1;" :: "l"(p), "r"(v) : "memory");
}
__device__ __forceinline__ void red_release_add(int* p, int v) {
    asm volatile("red.release.gpu.global.add.s32 [%0], %1;" :: "l"(p), "r"(v) : "memory");
}

// ---------------------------------------------------------------------------
// Shared-memory layouts per block role
// ---------------------------------------------------------------------------
struct FpsSmem {
    float4 c4[Nn];               // 128 KB staged coords
    ull    red[32];
    float4 q;
};

#define SW1_OFF  0               // float4[64]               -> 256 floats
#define SW2T_OFF 256             // float [64*64]  [c][o]    -> 4096 floats
#define SB2_OFF  (256 + 4096)               // float[64]
#define SW3_OFF  (256 + 4096 + 64)          // float[128*64] [o][c]
#define SB3_OFF  (256 + 4096 + 64 + 8192)   // float[128]
#define SMEM_FLOATS (256 + 4096 + 64 + 8192 + 128)

#define FUSED_SMEM ((int)(sizeof(FpsSmem) > SMEM_FLOATS * 4 ? sizeof(FpsSmem) : SMEM_FLOATS * 4))

// ---------------------------------------------------------------------------
// reset kernel: zero sync cells BEFORE the fused kernel, every launch
// (timed replays poison d_out; consumers must never see stale progress)
// ---------------------------------------------------------------------------
__global__ void reset_kernel()
{
    if (threadIdx.x < Bn) g_progress[threadIdx.x] = 0;
    if (threadIdx.x == 31) g_feat_done = 0;
}

// ---------------------------------------------------------------------------
// FUSED kernel, grid = 144 blocks x 1024 threads (1 block/SM, wave-1):
//   blocks 0..7    : FPS — publishes newxyz[b][it] + release progress[b]
//                    the moment center `it` is selected.
//   blocks 8..39   : per-point feature MLP (2048 pts/block) + release-add
//                    on g_feat_done when finished.
//   blocks 40..143 : persistent bq+pool consumer warps. Each warp owns <=3
//                    centers: acquire-poll progress (nanosleep backoff),
//                    exact bq scan, acquire feat_done, gather-max pool.
// Producers never wait on consumers -> deadlock-free by construction.
// ---------------------------------------------------------------------------
__global__ __launch_bounds__(1024, 1)
void fused_kernel(const float* __restrict__ xyz, float* __restrict__ newxyz_,
                  const float* __restrict__ w1, const float* __restrict__ b1,
                  const float* __restrict__ g1, const float* __restrict__ be1,
                  const float* __restrict__ m1, const float* __restrict__ v1,
                  const float* __restrict__ w2, const float* __restrict__ b2,
                  const float* __restrict__ g2, const float* __restrict__ be2,
                  const float* __restrict__ m2, const float* __restrict__ v2,
                  const float* __restrict__ w3, const float* __restrict__ b3,
                  const float* __restrict__ g3, const float* __restrict__ be3,
                  const float* __restrict__ m3, const float* __restrict__ v3,
                  float4* __restrict__ ft, float* __restrict__ feat)
{
    extern __shared__ char raw[];
    const int t = threadIdx.x;
    float* newxyz = newxyz_;          // strip restrict for cross-SM visibility

    if (blockIdx.x < Bn) {
        // =================== FPS role ========================================
        FpsSmem* sm = (FpsSmem*)raw;
        const int b = blockIdx.x;
        const int lane = t & 31, wid = t >> 5;
        const float* p = xyz + (size_t)b * Nn * 3;

        ull px2[4], py2[4], pz2[4];
        int mdi[PPT];
#pragma unroll
        for (int k = 0; k < 4; k++) {
            int i0 = t + (2 * k) * 1024;
            int i1 = i0 + 1024;
            px2[k] = pack2(p[3 * i0 + 0], p[3 * i1 + 0]);
            py2[k] = pack2(p[3 * i0 + 1], p[3 * i1 + 1]);
            pz2[k] = pack2(p[3 * i0 + 2], p[3 * i1 + 2]);
        }
#pragma unroll
        for (int j = 0; j < PPT; j++) mdi[j] = 0x7f800000;   // +inf bits

        for (int i = t; i < Nn; i += 1024)
            sm->c4[i] = make_float4(p[3 * i + 0], p[3 * i + 1], p[3 * i + 2], 0.f);
        if (t == 0) {
            // publish center 0 immediately
            float* o = newxyz + (size_t)b * NPOINT * 3;
            o[0] = p[0]; o[1] = p[1]; o[2] = p[2];
            st_release(&g_progress[b], 1);
        }
        __syncthreads();

        float4 q = sm->c4[0];

        for (int it = 1; it < NPOINT; it++) {
            ull nqx2 = pack2(-q.x, -q.x);
            ull nqy2 = pack2(-q.y, -q.y);
            ull nqz2 = pack2(-q.z, -q.z);

#pragma unroll
            for (int k = 0; k < 4; k++) {
                ull dx = add2(px2[k], nqx2);
                ull dy = add2(py2[k], nqy2);
                ull dz = add2(pz2[k], nqz2);
                ull s  = add2(add2(mul2(dx, dx), mul2(dy, dy)), mul2(dz, dz));
                float d0, d1; unpack2(s, d0, d1);
                mdi[2 * k]     = min(mdi[2 * k],     __float_as_int(d0));
                mdi[2 * k + 1] = min(mdi[2 * k + 1], __float_as_int(d1));
            }

            int m0 = max(mdi[0], mdi[1]);
            int m1 = max(mdi[2], mdi[3]);
            int m2 = max(mdi[4], mdi[5]);
            int m3 = max(mdi[6], mdi[7]);
            int m  = max(max(m0, m1), max(m2, m3));

            int wm = __reduce_max_sync(0xffffffffu, m);
            int cand = 0x7fffffff;
            if (m == wm) {
#pragma unroll
                for (int j = 0; j < PPT; j++)
                    if (mdi[j] == wm) cand = min(cand, t + j * 1024);
            }
            int widx = __reduce_min_sync(0xffffffffu, cand);
            if (lane == 0)
                sm->red[wid] = ((ull)(unsigned)wm << 32) | (unsigned)widx;
            __syncthreads();

            if (t < 32) {
                ull pk = sm->red[t];
                int v  = (int)(pk >> 32);
                int ix = (int)(unsigned)pk;
                int gm = __reduce_max_sync(0xffffffffu, v);
                int c2 = (v == gm) ? ix : 0x7fffffff;
                int win = __reduce_min_sync(0xffffffffu, c2);
                if (t == 0) {
                    float4 qq = sm->c4[win];
                    sm->q = qq;
                    float* o = newxyz + ((size_t)b * NPOINT + it) * 3;
                    o[0] = qq.x; o[1] = qq.y; o[2] = qq.z;
                    st_release(&g_progress[b], it + 1);
                }
            }
            __syncthreads();
            q = sm->q;
        }
    } else if (blockIdx.x < Bn + FEAT_BLOCKS) {
        // =================== feat role: per-point MLP, 2 pts/thread =========
        float*  smem = (float*)raw;
        float4* sw1  = (float4*)(smem + SW1_OFF);
        float*  sw2t = smem + SW2T_OFF;
        float*  sb2  = smem + SB2_OFF;
        float*  sw3  = smem + SW3_OFF;
        float*  sb3  = smem + SB3_OFF;

        for (int o = t; o < 64; o += 1024) {
            float s1 = g1[o] / sqrtf(v1[o] + 1e-5f);
            sw1[o] = make_float4(w1[o * 3 + 0] * s1, w1[o * 3 + 1] * s1,
                                 w1[o * 3 + 2] * s1, (b1[o] - m1[o]) * s1 + be1[o]);
            float s2 = g2[o] / sqrtf(v2[o] + 1e-5f);
            sb2[o] = (b2[o] - m2[o]) * s2 + be2[o];
        }
        for (int i = t; i < 64 * 64; i += 1024) {
            int o = i >> 6, c = i & 63;
            float s2 = g2[o] / sqrtf(v2[o] + 1e-5f);
            sw2t[c * 64 + o] = w2[o * 64 + c] * s2;   // transposed [c][o]
        }
        for (int i = t; i < 128 * 64; i += 1024) {
            int o = i >> 6;
            float s3 = g3[o] / sqrtf(v3[o] + 1e-5f);
            sw3[i] = w3[i] * s3;
        }
        for (int o = t; o < 128; o += 1024) {
            float s3 = g3[o] / sqrtf(v3[o] + 1e-5f);
            sb3[o] = (b3[o] - m3[o]) * s3 + be3[o];
        }
        __syncthreads();

        const int pbase = (blockIdx.x - Bn) * FEAT_PTS;

        for (int rep = 0; rep < FEAT_PTS / 1024; rep++) {
            const int pt = pbase + rep * 1024 + t;     // global point id
            const float x = __ldg(xyz + 3 * pt + 0);
            const float y = __ldg(xyz + 3 * pt + 1);
            const float z = __ldg(xyz + 3 * pt + 2);

            ull h2p[32];
            {
                const ull* sb2p = (const ull*)sb2;
#pragma unroll
                for (int k = 0; k < 32; k++) h2p[k] = sb2p[k];
            }

            for (int c = 0; c < 64; c++) {
                float4 wc = sw1[c];
                float h1 = fmaxf(fmaf(x, wc.x, fmaf(y, wc.y, fmaf(z, wc.z, wc.w))), 0.f);
                ull h1p = pack2(h1, h1);
                const ulonglong2* row = (const ulonglong2*)(sw2t + c * 64);
#pragma unroll
                for (int k = 0; k < 16; k++) {
                    ulonglong2 w = row[k];
                    h2p[2 * k]     = fma2(w.x, h1p, h2p[2 * k]);
                    h2p[2 * k + 1] = fma2(w.y, h1p, h2p[2 * k + 1]);
                }
            }
#pragma unroll
            for (int k = 0; k < 32; k++) {
                float a, c2; unpack2(h2p[k], a, c2);
                h2p[k] = pack2(fmaxf(a, 0.f), fmaxf(c2, 0.f));
            }

            float4* outr = ft + (size_t)pt * 32;
            for (int o4 = 0; o4 < 32; o4++) {
                float vv[4];
#pragma unroll
                for (int j = 0; j < 4; j++) {
                    int o = o4 * 4 + j;
                    const ulonglong2* row = (const ulonglong2*)(sw3 + o * 64);
                    ull a0 = 0ull, a1 = 0ull;
#pragma unroll
                    for (int k = 0; k < 16; k++) {
                        ulonglong2 w = row[k];
                        a0 = fma2(w.x, h2p[2 * k],     a0);
                        a1 = fma2(w.y, h2p[2 * k + 1], a1);
                    }
                    float s0, s1, s2, s3; unpack2(a0, s0, s1); unpack2(a1, s2, s3);
                    vv[j] = fmaxf((s0 + s1) + (s2 + s3) + sb3[o], 0.f);
                }
                outr[o4] = make_float4(vv[0], vv[1], vv[2], vv[3]);
            }
        }

        __syncthreads();                        // all block ft stores done
        if (t == 0) red_release_add(&g_feat_done, 1);
    } else {
        // =================== consumer role: bq + pool per center ============
        const int wid = t >> 5, lane = t & 31;
        const int cw = (blockIdx.x - (Bn + FEAT_BLOCKS)) * 32 + wid;  // 0..3327
        int* myidx = ((int*)raw) + wid * NSAMPLE;

        for (int rep = 0; rep < 3; rep++) {
            const int c = cw + rep * CONS_WARPS;
            if (c >= Bn * NPOINT) break;
            const int b = c >> 10;
            const int s = c & 1023;

            // wait until FPS publishes this center (acquire + sleep backoff)
            for (;;) {
                int pr = ld_acquire(&g_progress[b]);
                if (pr > s) break;
                __nanosleep(512);
            }
            __syncwarp();

            // ball query scan (exact reference arithmetic, early exit)
            const float* p = xyz + (size_t)b * Nn * 3;
            const float qx = newxyz[3 * c + 0];
            const float qy = newxyz[3 * c + 1];
            const float qz = newxyz[3 * c + 2];

            int cnt = 0;
            for (int base = 0; base < Nn; base += 32) {
                const int i = base + lane;
                float dx = __fadd_rn(__ldg(p + 3 * i + 0), -qx);
                float dy = __fadd_rn(__ldg(p + 3 * i + 1), -qy);
                float dz = __fadd_rn(__ldg(p + 3 * i + 2), -qz);
                float d  = __fadd_rn(__fadd_rn(__fmul_rn(dx, dx), __fmul_rn(dy, dy)),
                                     __fmul_rn(dz, dz));
                const bool valid = d < 0.04f;
                const unsigned mask = __ballot_sync(0xffffffffu, valid);
                if (valid) {
                    int pos = cnt + __popc(mask & ((1u << lane) - 1u));
                    if (pos < NSAMPLE) myidx[pos] = i;
                }
                cnt += __popc(mask);
                if (cnt >= NSAMPLE) break;
            }
            if (cnt < NSAMPLE) {               // reference pads with 0
                int sl = cnt + lane;
                if (sl < NSAMPLE) myidx[sl] = 0;
            }
            __syncwarp();

            // wait for the feature table (usually already done)
            for (;;) {
                int fd = ld_acquire(&g_feat_done);
                if (fd >= FEAT_BLOCKS) break;
                __nanosleep(512);
            }
            __syncwarp();

            // gather-max pool: lane owns 4 channels
            const float4* base4 = ft + ((size_t)b * Nn) * 32;
            float4 mx = make_float4(0.f, 0.f, 0.f, 0.f);
#pragma unroll 4
            for (int smp = 0; smp < NSAMPLE; smp++) {
                int is = myidx[smp];                       // broadcast LDS
                float4 v = __ldg(base4 + (size_t)is * 32 + lane);
                mx.x = fmaxf(mx.x, v.x);
                mx.y = fmaxf(mx.y, v.y);
                mx.z = fmaxf(mx.z, v.z);
                mx.w = fmaxf(mx.w, v.w);
            }

            float* o = feat + ((size_t)b * 128 + lane * 4) * NPOINT + s;
            o[0 * NPOINT] = mx.x;
            o[1 * NPOINT] = mx.y;
            o[2 * NPOINT] = mx.z;
            o[3 * NPOINT] = mx.w;
        }
    }
}

// ---------------------------------------------------------------------------
extern "C" void kernel_launch(void* const* d_in, const int* in_sizes, int n_in,
                              void* d_out, int out_size)
{
    const float* xyz = (const float*)d_in[0];
    const float* w1  = (const float*)d_in[1];
    const float* b1  = (const float*)d_in[2];
    const float* g1  = (const float*)d_in[3];
    const float* be1 = (const float*)d_in[4];
    const float* m1  = (const float*)d_in[5];
    const float* v1  = (const float*)d_in[6];
    const float* w2  = (const float*)d_in[7];
    const float* b2  = (const float*)d_in[8];
    const float* g2  = (const float*)d_in[9];
    const float* be2 = (const float*)d_in[10];
    const float* m2  = (const float*)d_in[11];
    const float* v2  = (const float*)d_in[12];
    const float* w3  = (const float*)d_in[13];
    const float* b3  = (const float*)d_in[14];
    const float* g3  = (const float*)d_in[15];
    const float* be3 = (const float*)d_in[16];
    const float* m3  = (const float*)d_in[17];
    const float* v3  = (const float*)d_in[18];

    float* out    = (float*)d_out;
    float* newxyz = out;                             // (B, NPOINT, 3)
    float* feat   = out + (size_t)Bn * NPOINT * 3;   // (B, 128, NPOINT)

    float4* ft = nullptr;
    cudaGetSymbolAddress((void**)&ft, g_feat4);

    cudaFuncSetAttribute(fused_kernel,
                         cudaFuncAttributeMaxDynamicSharedMemorySize, FUSED_SMEM);

    reset_kernel<<<1, 32>>>();
    fused_kernel<<<GRID_TOTAL, 1024, FUSED_SMEM>>>(
        xyz, newxyz,
        w1, b1, g1, be1, m1, v1,
        w2, b2, g2, be2, m2, v2,
        w3, b3, g3, be3, m3, v3,
        ft, feat);
}